// round 2
// baseline (speedup 1.0000x reference)
#include <cuda_runtime.h>
#include <cstdint>

#define N_BOX 16384
#define FEAT 512
#define NUM_CATS 65
#define KSEL 25
#define MAX_DETS 1000
#define NMS_THRESH 0.6f
#define MIN_RPN 0.9f
#define MIN_AREA 220.0f
#define ROW_WORDS 512   /* 16384/32 */

// ---------------- device scratch (no allocations allowed) ----------------
__device__ int g_M;
__device__ unsigned long long g_keys[N_BOX];
__device__ int   g_sortedIdx[N_BOX];
__device__ float4 g_sortedBox[N_BOX];
__device__ float g_area[N_BOX];
__device__ unsigned g_mat[(size_t)N_BOX * ROW_WORDS];   // 32 MB suppression bitmask

// ---------------- kernel 0: zero the compaction counter ----------------
__global__ void kZero() { g_M = 0; }

// ---------------- kernel 1: compact boxes with score >= 0.9 ----------------
__global__ void kCompact(const float* __restrict__ scores) {
    int stride = gridDim.x * blockDim.x;
    for (int i = blockIdx.x * blockDim.x + threadIdx.x; i < N_BOX; i += stride) {
        float s = scores[i];
        if (s >= MIN_RPN) {
            int p = atomicAdd(&g_M, 1);
            // key: score descending (positive floats -> bits monotone), then index ascending
            g_keys[p] = ((unsigned long long)(0xFFFFFFFFu - __float_as_uint(s)) << 32)
                        | (unsigned)i;
        }
    }
}

// ---------------- kernel 2: single-block bitonic sort of keys ----------------
extern __shared__ unsigned long long s_keys[];
__global__ void kSort(const float* __restrict__ det_boxes) {
    int M = g_M;
    int P = 2;
    while (P < M) P <<= 1;
    const unsigned long long PADK = 0xFFFFFFFFFFFFFFFFULL;

    for (int t = threadIdx.x; t < P; t += blockDim.x)
        s_keys[t] = (t < M) ? g_keys[t] : PADK;
    __syncthreads();

    for (int k = 2; k <= P; k <<= 1) {
        for (int j = k >> 1; j > 0; j >>= 1) {
            for (int t = threadIdx.x; t < P; t += blockDim.x) {
                int ixj = t ^ j;
                if (ixj > t) {
                    bool up = ((t & k) == 0);
                    unsigned long long a = s_keys[t], b = s_keys[ixj];
                    if ((a > b) == up) { s_keys[t] = b; s_keys[ixj] = a; }
                }
            }
            __syncthreads();
        }
    }

    for (int t = threadIdx.x; t < M; t += blockDim.x) {
        int orig = (int)(s_keys[t] & 0xFFFFFFFFu);
        g_sortedIdx[t] = orig;
        float4 b = ((const float4*)det_boxes)[orig];   // [y1, x1, y2, x2]
        g_sortedBox[t] = b;
        g_area[t] = (b.w - b.y) * (b.z - b.x);         // (x2-x1)*(y2-y1)
    }
}

// ---------------- kernel 3: pairwise IoU suppression bitmask ----------------
__global__ void kMatrix() {
    int M = g_M;
    int Mw = (M + 31) >> 5;
    int total = M * Mw;
    int stride = gridDim.x * blockDim.x;
    for (int it = blockIdx.x * blockDim.x + threadIdx.x; it < total; it += stride) {
        int i = it / Mw;
        int w = it - i * Mw;
        float4 bi = g_sortedBox[i];
        float ai = g_area[i];
        unsigned bits = 0;
        int j0 = w * 32;
        int jend = min(32, M - j0);
        for (int jj = 0; jj < jend; ++jj) {
            int j = j0 + jj;
            if (j <= i) continue;
            float4 bj = g_sortedBox[j];
            float iw = fmaxf(0.0f, fminf(bi.w, bj.w) - fmaxf(bi.y, bj.y));
            float ih = fmaxf(0.0f, fminf(bi.z, bj.z) - fmaxf(bi.x, bj.x));
            float inter = iw * ih;
            float iou = inter / (ai + g_area[j] - inter + 1e-12f);
            if (iou > NMS_THRESH) bits |= (1u << jj);
        }
        g_mat[(size_t)i * ROW_WORDS + w] = bits;
    }
}

// ---------------- kernel 4: scan + select + GEMM + sort + outputs ----------------
__global__ void kFinal(const float* __restrict__ roi_boxes,
                       const float* __restrict__ det_boxes,
                       const float* __restrict__ vis,
                       const float* __restrict__ img_info,
                       const float* __restrict__ txt,
                       float* __restrict__ out) {
    __shared__ unsigned sh_removed[ROW_WORDS];
    __shared__ unsigned sh_keep[ROW_WORDS];
    __shared__ unsigned sh_flags[ROW_WORDS];
    __shared__ int      sh_scan[ROW_WORDS];
    __shared__ unsigned sh_chunk[32];
    __shared__ int      sh_cnt;
    __shared__ int      sh_count;
    __shared__ int      sh_idx[KSEL];
    __shared__ float    S[KSEL][NUM_CATS];
    __shared__ float    sh_key[KSEL];
    __shared__ int      sh_src[KSEL];
    __shared__ unsigned char sh_fg[KSEL];

    const int tid = threadIdx.x;
    const int nthr = blockDim.x;
    const int M  = g_M;
    const int Mw = (M + 31) >> 5;

    for (int t = tid; t < ROW_WORDS; t += nthr) {
        sh_removed[t] = 0; sh_keep[t] = 0; sh_flags[t] = 0;
    }
    if (tid == 0) sh_cnt = 0;
    __syncthreads();

    // ---- chunked greedy NMS scan (32 sorted boxes per chunk) ----
    for (int c = 0; c < Mw; ++c) {
        if (sh_cnt >= MAX_DETS) break;            // uniform
        if (tid < 32) {
            int gi = c * 32 + tid;
            sh_chunk[tid] = (gi < M) ? g_mat[(size_t)gi * ROW_WORDS + c] : 0u;
        }
        __syncthreads();
        if (tid == 0) {
            unsigned rem = sh_removed[c];
            unsigned km = 0;
            int cnt = sh_cnt;
            int lim = min(32, M - c * 32);
            for (int i = 0; i < lim && cnt < MAX_DETS; ++i) {
                if (!((rem >> i) & 1u)) {
                    km |= (1u << i);
                    ++cnt;
                    rem |= sh_chunk[i];           // intra-chunk suppression (bits j>i only)
                }
            }
            sh_removed[c] = rem;
            sh_keep[c] = km;
            sh_cnt = cnt;
        }
        __syncthreads();
        unsigned km = sh_keep[c];                 // uniform
        if (km) {
            for (int w = c + 1 + tid; w < Mw; w += nthr) {
                unsigned acc = sh_removed[w];
                unsigned m = km;
                while (m) {
                    int i = __ffs(m) - 1; m &= m - 1;
                    acc |= g_mat[(size_t)(c * 32 + i) * ROW_WORDS + w];
                }
                sh_removed[w] = acc;
            }
        }
        __syncthreads();
    }

    // ---- valid flags on ORIGINAL indices (keep & rpn & area & nonzero roi) ----
    const float sy = img_info[4];   // image_info[2][0]
    const float sx = img_info[5];   // image_info[2][1]
    for (int t = tid; t < M; t += nthr) {
        if ((sh_keep[t >> 5] >> (t & 31)) & 1u) {
            int orig = g_sortedIdx[t];
            float4 rb = ((const float4*)roi_boxes)[orig];
            bool allz = (rb.x == 0.f && rb.y == 0.f && rb.z == 0.f && rb.w == 0.f);
            float4 db = ((const float4*)det_boxes)[orig];
            float area = (db.z / sy - db.x / sy) * (db.w / sx - db.y / sx);
            if (!allz && area > MIN_AREA)
                atomicOr(&sh_flags[orig >> 5], 1u << (orig & 31));
        }
    }
    __syncthreads();

    // ---- first 25 valid indices in ascending original order (prefix scan) ----
    if (tid < ROW_WORDS) sh_scan[tid] = __popc(sh_flags[tid]);
    __syncthreads();
    for (int off = 1; off < ROW_WORDS; off <<= 1) {
        int v = (tid < ROW_WORDS && tid >= off) ? sh_scan[tid - off] : 0;
        __syncthreads();
        if (tid < ROW_WORDS) sh_scan[tid] += v;
        __syncthreads();
    }
    if (tid < KSEL) sh_idx[tid] = 0;              // jnp.nonzero fill_value = 0
    if (tid == 0) sh_count = sh_scan[ROW_WORDS - 1];
    __syncthreads();
    if (tid < ROW_WORDS) {
        int excl = sh_scan[tid] - __popc(sh_flags[tid]);
        if (excl < KSEL) {
            unsigned f = sh_flags[tid];
            int r = excl;
            while (f && r < KSEL) {
                int b = __ffs(f) - 1; f &= f - 1;
                sh_idx[r] = tid * 32 + b;
                ++r;
            }
        }
    }
    __syncthreads();

    // ---- GEMM: S[25][65] = vis[idx] @ txt^T ----
    for (int p = tid; p < KSEL * NUM_CATS; p += nthr) {
        int r = p / NUM_CATS, c = p - r * NUM_CATS;
        const float4* vf = (const float4*)(vis + (size_t)sh_idx[r] * FEAT);
        const float4* tf = (const float4*)(txt + (size_t)c * FEAT);
        float acc = 0.f;
#pragma unroll 8
        for (int q = 0; q < FEAT / 4; ++q) {
            float4 a = vf[q], b = tf[q];
            acc += a.x * b.x + a.y * b.y + a.z * b.z + a.w * b.w;
        }
        S[r][c] = acc;
    }
    __syncthreads();

    // ---- per-row max / argmax, fg, sort key ----
    if (tid < KSEL) {
        float mx = S[tid][0]; int am = 0;
        for (int c = 1; c < NUM_CATS; ++c) {
            float v = S[tid][c];
            if (v > mx) { mx = v; am = c; }       // first-occurrence argmax
        }
        bool rv = tid < min(sh_count, KSEL);
        bool fg = rv && (am != 0);
        sh_fg[tid] = fg ? 1 : 0;
        sh_key[tid] = fg ? mx : __int_as_float(0xff800000);  // -inf
    }
    __syncthreads();

    // ---- stable descending argsort via rank (ties -> index ascending) ----
    if (tid < KSEL) {
        float k = sh_key[tid];
        int rank = 0;
        for (int j = 0; j < KSEL; ++j) {
            float kj = sh_key[j];
            if (kj > k || (kj == k && j < tid)) ++rank;
        }
        sh_src[rank] = tid;
    }
    __syncthreads();

    // ---- outputs: scores (25x64) | bboxes (25x4) | mask (25) ----
    for (int p = tid; p < KSEL * (NUM_CATS - 1); p += nthr) {
        int row = p / (NUM_CATS - 1), c = p - row * (NUM_CATS - 1);
        int s = sh_src[row];
        out[p] = sh_fg[s] ? S[s][c + 1] : 0.f;
    }
    if (tid < KSEL) {
        int s = sh_src[tid];
        bool m = sh_fg[s] != 0;
        float4 db = ((const float4*)det_boxes)[sh_idx[s]];
        float xmin = db.y / sx, ymin = db.x / sy, xmax = db.w / sx, ymax = db.z / sy;
        float* o = out + KSEL * (NUM_CATS - 1) + tid * 4;
        o[0] = m ? xmin : 0.f;
        o[1] = m ? ymin : 0.f;
        o[2] = m ? xmax : 0.f;
        o[3] = m ? ymax : 0.f;
        out[KSEL * (NUM_CATS - 1) + KSEL * 4 + tid] = m ? 1.f : 0.f;
    }
}

// ---------------- launch ----------------
extern "C" void kernel_launch(void* const* d_in, const int* in_sizes, int n_in,
                              void* d_out, int out_size) {
    const float* roi_boxes  = (const float*)d_in[0];
    const float* roi_scores = (const float*)d_in[1];
    const float* det_boxes  = (const float*)d_in[2];
    /* d_in[3]: detection_masks — unused by reference outputs */
    const float* vis        = (const float*)d_in[4];
    const float* img_info   = (const float*)d_in[5];
    const float* txt        = (const float*)d_in[6];
    float* out = (float*)d_out;

    kZero<<<1, 1>>>();
    kCompact<<<64, 256>>>(roi_scores);
    cudaFuncSetAttribute(kSort, cudaFuncAttributeMaxDynamicSharedMemorySize, 131072);
    kSort<<<1, 1024, 131072>>>(det_boxes);
    kMatrix<<<1024, 256>>>();
    kFinal<<<1, 1024>>>(roi_boxes, det_boxes, vis, img_info, txt, out);
}